// round 12
// baseline (speedup 1.0000x reference)
#include <cuda_runtime.h>
#include <cuda_fp16.h>
#include <cstdint>

// ===========================================================================
// CharLSTMEmbedding: B=32, T=128, L=16, VOCAB=256, E=256, H=512
// sm_103 plain target -> mma.sync HMMA + cp.async.bulk loads.
//
// R11: ONE persistent kernel for all 15 recurrent steps.
//  * tiles dealt round-robin over the whole run (balanced ~13 tiles/CTA)
//  * no global barrier: chunk ck of tile (mx,*) at step t depends ONLY on
//    tile (mx, nx=ck) of step t-1 (n' permutation makes the hc ranges line
//    up exactly with A K-chunks) -> per-tile done[mx][nx] flags, dataflow.
//  * removes per-step wave quantization (21 -> ~13 round-equivalents) and
//    15x launch overhead.
// Everything else (hi/lo fp16 3-term HMMA, bulk-copy pipeline, sorted active
// prefix, fused epilogue) as R10.
// ===========================================================================

#define BT   4096
#define SL   16
#define HD   512
#define ED   256
#define NV   256
#define G4   2048

#define TIL  8192              // one 128x32-half tile (hi or lo)
#define CK2  16384             // hi+lo pair
#define NCK  16                // K chunks of 32

__device__ __align__(1024) unsigned char g_W[16 * NCK * CK2];     // 4 MB
__device__ __align__(1024) unsigned char g_A[2][32 * NCK * CK2];  // 2 x 8 MB
__device__ __align__(256) float g_tbl[NV * G4];                   // 2 MB
__device__ __align__(256) float g_C[BT * HD];                     // 8 MB
__device__ int g_perm[BT];      // sorted-pos -> original row
__device__ int g_lens_s[BT];    // lens in sorted order (descending)
__device__ int g_Mt[SL];        // M_t = #(lens > t)
__device__ int g_done[32][16];  // highest step whose (mx,nx) epilogue is done

// ------------------------------ helpers -----------------------------------

__device__ __forceinline__ uint32_t smem_u32(const void* p) {
    uint32_t a;
    asm("{ .reg .u64 t; cvta.to.shared.u64 t, %1; cvt.u32.u64 %0, t; }"
        : "=r"(a) : "l"(p));
    return a;
}

// paired-row swizzle for 128row x 64B tiles
__device__ __forceinline__ uint32_t swz32(uint32_t r, uint32_t x) {
    return (r >> 1) * 128u + ((((r & 1u) << 6) + x) ^ ((r & 14u) << 3));
}

__device__ __forceinline__ void bulk_cp(uint32_t dst, const void* src,
                                        uint32_t bytes, uint32_t mbar) {
    asm volatile(
        "cp.async.bulk.shared::cluster.global.mbarrier::complete_tx::bytes "
        "[%0], [%1], %2, [%3];"
        :: "r"(dst), "l"(src), "r"(bytes), "r"(mbar) : "memory");
}

__device__ __forceinline__ void mbar_init(uint32_t mbar, uint32_t cnt) {
    asm volatile("mbarrier.init.shared.b64 [%0], %1;" :: "r"(mbar), "r"(cnt)
                 : "memory");
}
__device__ __forceinline__ void mbar_expect(uint32_t mbar, uint32_t bytes) {
    asm volatile("mbarrier.arrive.expect_tx.shared.b64 _, [%0], %1;"
                 :: "r"(mbar), "r"(bytes) : "memory");
}
__device__ __forceinline__ void mbar_arrive(uint32_t mbar) {
    asm volatile("mbarrier.arrive.shared.b64 _, [%0];" :: "r"(mbar) : "memory");
}
__device__ __forceinline__ void mbar_wait(uint32_t mbar, uint32_t parity) {
    asm volatile(
        "{\n\t.reg .pred P;\n\t"
        "WL_%=:\n\t"
        "mbarrier.try_wait.parity.acquire.cta.shared::cta.b64 P, [%0], %1, 0x989680;\n\t"
        "@P bra.uni WD_%=;\n\t"
        "bra.uni WL_%=;\n\t"
        "WD_%=:\n\t}"
        :: "r"(mbar), "r"(parity) : "memory");
}

__device__ __forceinline__ void ldsm4(uint32_t* r, uint32_t addr) {
    asm volatile("ldmatrix.sync.aligned.m8n8.x4.shared.b16 {%0,%1,%2,%3}, [%4];"
                 : "=r"(r[0]), "=r"(r[1]), "=r"(r[2]), "=r"(r[3]) : "r"(addr));
}
__device__ __forceinline__ void ldsm2(uint32_t* r, uint32_t addr) {
    asm volatile("ldmatrix.sync.aligned.m8n8.x2.shared.b16 {%0,%1}, [%2];"
                 : "=r"(r[0]), "=r"(r[1]) : "r"(addr));
}

__device__ __forceinline__ void mma16816(float* d, const uint32_t* a,
                                         const uint32_t* b) {
    asm volatile(
        "mma.sync.aligned.m16n8k16.row.col.f32.f16.f16.f32 "
        "{%0,%1,%2,%3}, {%4,%5,%6,%7}, {%8,%9}, {%0,%1,%2,%3};"
        : "+f"(d[0]), "+f"(d[1]), "+f"(d[2]), "+f"(d[3])
        : "r"(a[0]), "r"(a[1]), "r"(a[2]), "r"(a[3]), "r"(b[0]), "r"(b[1]));
}

__device__ __forceinline__ float sigf(float x) {
    return __fdividef(1.0f, 1.0f + __expf(-x));
}
__device__ __forceinline__ float tanhfast(float x) {
    return __fdividef(2.0f, 1.0f + __expf(-2.0f * x)) - 1.0f;
}

// ------------------------------ prep kernels ------------------------------

// counting sort by length, descending; also resets dataflow flags.
__global__ void prep_perm(const int* __restrict__ lens) {
    __shared__ int cnt[17], off[17];
    int tid = threadIdx.x;
    if (tid < 17) cnt[tid] = 0;
    ((int*)g_done)[tid] = 0;                     // 512 flags reset (step0 = done)
    __syncthreads();
    for (int i = tid; i < BT; i += 512) atomicAdd(&cnt[lens[i]], 1);
    __syncthreads();
    if (tid == 0) {
        int acc = 0;
        for (int l = 16; l >= 1; l--) { off[l] = acc; acc += cnt[l]; }
        g_Mt[0] = BT;
        for (int t = 1; t < SL; t++) g_Mt[t] = off[t];   // #(lens > t)
    }
    __syncthreads();
    int w = tid >> 5, lane = tid & 31;
    int l = w + 1;                                   // bins 1..16
    int p = off[l];
    for (int base = 0; base < BT; base += 32) {
        int i = base + lane;
        bool m = (lens[i] == l);
        unsigned msk = __ballot_sync(0xffffffffu, m);
        if (m) {
            int rank = __popc(msk & ((1u << lane) - 1));
            g_perm[p + rank] = i;
            g_lens_s[p + rank] = l;
        }
        p += __popc(msk);
    }
}

__global__ void prep_w(const float* __restrict__ W) {
    int idx = blockIdx.x * 256 + threadIdx.x;      // < G4*HD
    int np = idx >> 9, k = idx & 511;
    int hc = ((np >> 5) << 3) + (np & 7);
    int g  = (np >> 3) & 3;
    float v = W[(g * HD + hc) * HD + k];
    __half hi = __float2half_rn(v);
    __half lo = __float2half_rn(v - __half2float(hi));
    uint32_t base = (uint32_t)((np >> 7) * NCK + (k >> 5)) * CK2;
    uint32_t off  = swz32((uint32_t)(np & 127), (uint32_t)((k & 31) * 2));
    *(__half*)(g_W + base + off)       = hi;
    *(__half*)(g_W + base + TIL + off) = lo;
}

__global__ void prep_tbl(const float* __restrict__ emb,
                         const float* __restrict__ Wih,
                         const float* __restrict__ bi,
                         const float* __restrict__ bh) {
    __shared__ __align__(16) float e[ED];
    int v = blockIdx.y;
    for (int i = threadIdx.x; i < ED; i += blockDim.x)
        e[i] = emb[v * ED + i];
    __syncthreads();

    int np = blockIdx.x * 128 + threadIdx.x;
    int hc = ((np >> 5) << 3) + (np & 7);
    int g  = (np >> 3) & 3;
    int n  = g * HD + hc;
    const float4* w4 = (const float4*)(Wih + n * ED);
    const float4* e4 = (const float4*)e;
    float s = bi[n] + bh[n];
#pragma unroll 8
    for (int k = 0; k < ED / 4; k++) {
        float4 wv = w4[k];
        float4 ev = e4[k];
        s += ev.x * wv.x + ev.y * wv.y + ev.z * wv.z + ev.w * wv.w;
    }
    g_tbl[v * G4 + np] = s;
}

// step 0 in sorted row space; rows with lens==1 freeze here -> write out
__global__ void step0(const int* __restrict__ seq, float* __restrict__ out) {
    int ms = blockIdx.x;                       // sorted row
    int hc = blockIdx.y * 128 + threadIdx.x;
    int orig = g_perm[ms];
    int id = seq[orig * SL];
    int base = ((hc >> 3) << 5) + (hc & 7);    // gate stride 8 in tbl
    const float* tr = g_tbl + id * G4;
    float cn = sigf(tr[base]) * tanhfast(tr[base + 16]);
    float hn = sigf(tr[base + 24]) * tanhfast(cn);
    __half hi = __float2half_rn(hn);
    __half lo = __float2half_rn(hn - __half2float(hi));
    uint32_t tb  = (uint32_t)((ms >> 7) * NCK + (hc >> 5)) * CK2;
    uint32_t off = swz32((uint32_t)(ms & 127), (uint32_t)((hc & 31) * 2));
    *(__half*)(g_A[0] + tb + off)       = hi;
    *(__half*)(g_A[0] + tb + TIL + off) = lo;
    g_C[ms * HD + hc] = cn;
    if (g_lens_s[ms] == 1) out[orig * HD + hc] = hn;
}

// ----------------------- persistent recurrent kernel ----------------------
// grid = 2 * SM count, all CTAs resident (launch_bounds(256,2), 97KB smem).
// CTA tile 128(m) x 128(n'), 8 warps (2m x 4n), warp 64x32, K chunks of 32.

#define SMEM_TOTAL (1024 + 3 * 32768)

__global__ void __launch_bounds__(256, 2)
lstm_persist(const int* __restrict__ seq, float* __restrict__ out_f, int ncta) {
    extern __shared__ char smem[];
    const uint32_t sb = smem_u32(smem);
    const int cta = blockIdx.x;
    const int tid = threadIdx.x, lid = tid & 31;
    const int wm = (tid >> 5) >> 2;            // 0..1
    const int wn = (tid >> 5) & 3;             // 0..3

    if (tid == 0) {
#pragma unroll
        for (int b = 0; b < 3; b++) {
            mbar_init(sb + b * 8, 1);          // full (tx-based)
            mbar_init(sb + 24 + b * 8, 8);     // empty (8 warp arrives)
        }
    }
    __syncthreads();

    const uint32_t arow = (uint32_t)(wm * 64 + (lid & 15));
    const uint32_t acs  = (uint32_t)((lid >> 4) * 16);
    const uint32_t brow = (uint32_t)(wn * 32 + (lid & 7));
    const uint32_t bcs  = (uint32_t)(((lid >> 3) & 1) * 16);
    const int q_ep = lid & 3, r_ep = lid >> 2;

    float acc[4][4][4];
    int qg = 0;        // global chunk sequence number for this CTA
    int P  = 0;        // tile-deal prefix (mod ncta)

    for (int t = 1; t < SL; t++) {
        const unsigned char* __restrict__ Abase = g_A[(t + 1) & 1];
        unsigned char* __restrict__ Aout = g_A[t & 1];
        const unsigned char* __restrict__ Ain = Abase;
        const int Mpad = (g_Mt[t] + 127) & ~127;
        const int ntiles = (Mpad >> 7) * 16;
        int o = (cta - P) % ncta; if (o < 0) o += ncta;
        const int mytiles = (o < ntiles) ? ((ntiles - 1 - o) / ncta + 1) : 0;
        const int n_me = mytiles << 4;

        auto issue_chunk = [&](int j) {
            const int q = qg + j;
            const int tile = o + (j >> 4) * ncta;
            const int mx = tile >> 4, nx = tile & 15, ck = j & 15;
            if (t > 1) {      // producer tile (mx, nx=ck) of step t-1 done?
                while (*(volatile int*)&g_done[mx][ck] < t - 1)
                    __nanosleep(64);
            }
            __threadfence();
            asm volatile("fence.proxy.async;" ::: "memory");
            const int u = q / 3;
            const uint32_t buf = (uint32_t)(q % 3);
            if (u > 0) mbar_wait(sb + 24 + buf * 8, (uint32_t)((u - 1) & 1));
            const uint32_t dst = sb + 1024 + buf * 32768;
            const uint32_t mb  = sb + buf * 8;
            mbar_expect(mb, 32768);
            bulk_cp(dst,       Abase + ((size_t)mx * NCK + ck) * CK2, CK2, mb);
            bulk_cp(dst + CK2, g_W   + ((size_t)nx * NCK + ck) * CK2, CK2, mb);
        };

        if (tid == 0) {
            const int pre = n_me < 3 ? n_me : 3;
            for (int jj = 0; jj < pre; jj++) issue_chunk(jj);
        }

        for (int j = 0; j < n_me; j++) {
            if ((j & 15) == 0) {
#pragma unroll
                for (int a = 0; a < 4; a++)
#pragma unroll
                    for (int b = 0; b < 4; b++)
#pragma unroll
                        for (int c = 0; c < 4; c++) acc[a][b][c] = 0.0f;
            }
            const int q = qg + j;
            const uint32_t buf = (uint32_t)(q % 3);
            mbar_wait(sb + buf * 8, (uint32_t)((q / 3) & 1));

            const uint32_t cb = sb + 1024 + buf * 32768;
            const uint32_t sAhi = cb, sAlo = cb + TIL;
            const uint32_t sBhi = cb + 2 * TIL, sBlo = cb + 3 * TIL;

#pragma unroll
            for (int k16 = 0; k16 < 2; k16++) {
                const uint32_t ax = (uint32_t)(k16 * 32) + acs;
                const uint32_t bx = (uint32_t)(k16 * 32) + bcs;
                uint32_t bhf[4][2], blf[4][2];
#pragma unroll
                for (int g = 0; g < 4; g++) {
                    uint32_t ro = swz32(brow + (uint32_t)(g * 8), bx);
                    ldsm2(bhf[g], sBhi + ro);
                    ldsm2(blf[g], sBlo + ro);
                }
#pragma unroll
                for (int mt = 0; mt < 4; mt++) {
                    uint32_t ro = swz32(arow + (uint32_t)(mt * 16), ax);
                    uint32_t ah[4], al[4];
                    ldsm4(ah, sAhi + ro);
                    ldsm4(al, sAlo + ro);
#pragma unroll
                    for (int g = 0; g < 4; g++) mma16816(acc[mt][g], ah, bhf[g]);
#pragma unroll
                    for (int g = 0; g < 4; g++) mma16816(acc[mt][g], ah, blf[g]);
#pragma unroll
                    for (int g = 0; g < 4; g++) mma16816(acc[mt][g], al, bhf[g]);
                }
            }
            if (lid == 0) mbar_arrive(sb + 24 + buf * 8);
            if (tid == 0 && j + 3 < n_me) issue_chunk(j + 3);

            if ((j & 15) == 15) {
                // ------------- fused LSTM epilogue for this tile -------------
                const int tile = o + (j >> 4) * ncta;
                const int mx = tile >> 4, nx = tile & 15;
                const int m0 = mx * 128, n0 = nx * 128;
                const int cn0 = n0 + wn * 32;
                const int hcb = (cn0 >> 2) + 2 * q_ep;
                const uint32_t ckh  = (uint32_t)(hcb >> 5);
                const uint32_t xoff = (uint32_t)((hcb & 31) * 2);

#pragma unroll
                for (int mt = 0; mt < 4; mt++) {
#pragma unroll
                    for (int v = 0; v < 2; v++) {
                        const int ms = m0 + wm * 64 + mt * 16 + r_ep + v * 8;
                        const int L  = g_lens_s[ms];
                        const bool act = L > t;
                        const uint32_t tb =
                            ((uint32_t)(ms >> 7) * NCK + ckh) * CK2;
                        const uint32_t off = swz32((uint32_t)(ms & 127), xoff);
                        __half2* phiO = (__half2*)(Aout + tb + off);
                        __half2* ploO = (__half2*)(Aout + tb + TIL + off);
                        if (act) {
                            const int orig = g_perm[ms];
                            const int id = seq[orig * SL + t];
                            const float* tr =
                                g_tbl + id * G4 + cn0 + 2 * q_ep;
                            float2 cp = *(const float2*)(g_C + ms * HD + hcb);
                            float co[2] = {cp.x, cp.y};
                            float h2[2], c2[2];
#pragma unroll
                            for (int jj = 0; jj < 2; jj++) {
                                float pi = acc[mt][0][2 * v + jj] + tr[0 + jj];
                                float pf = acc[mt][1][2 * v + jj] + tr[8 + jj];
                                float pg = acc[mt][2][2 * v + jj] + tr[16 + jj];
                                float po = acc[mt][3][2 * v + jj] + tr[24 + jj];
                                float ig = sigf(pi), fg = sigf(pf);
                                float gg = tanhfast(pg), og = sigf(po);
                                float cc = fg * co[jj] + ig * gg;
                                c2[jj] = cc;
                                h2[jj] = og * tanhfast(cc);
                            }
                            *(float2*)(g_C + ms * HD + hcb) =
                                make_float2(c2[0], c2[1]);
                            __half hi0 = __float2half_rn(h2[0]);
                            __half hi1 = __float2half_rn(h2[1]);
                            __half lo0 = __float2half_rn(h2[0] - __half2float(hi0));
                            __half lo1 = __float2half_rn(h2[1] - __half2float(hi1));
                            *phiO = __halves2half2(hi0, hi1);
                            *ploO = __halves2half2(lo0, lo1);
                            if (L == t + 1)
                                *(float2*)(out_f + orig * HD + hcb) =
                                    make_float2(h2[0], h2[1]);
                        } else {
                            *phiO = *(const __half2*)(Ain + tb + off);
                            *ploO = *(const __half2*)(Ain + tb + TIL + off);
                        }
                    }
                }
                __syncthreads();          // all warps' epilogue writes done
                if (tid == 0) {
                    __threadfence();
                    atomicExch(&g_done[mx][nx], t);   // release tile
                }
            }
        }
        qg += n_me;
        P = (P + ntiles) % ncta;
    }
}

// ------------------------------ host entry --------------------------------
// Inputs: char_seq_padded(i32), char_lengths(i32), emb, W_ih, W_hh, b_ih, b_hh
extern "C" void kernel_launch(void* const* d_in, const int* in_sizes, int n_in,
                              void* d_out, int out_size) {
    const int*   seq  = (const int*)  d_in[0];
    const int*   lens = (const int*)  d_in[1];
    const float* emb  = (const float*)d_in[2];
    const float* W_ih = (const float*)d_in[3];
    const float* W_hh = (const float*)d_in[4];
    const float* b_ih = (const float*)d_in[5];
    const float* b_hh = (const float*)d_in[6];
    float* out = (float*)d_out;

    cudaFuncSetAttribute(lstm_persist,
                         cudaFuncAttributeMaxDynamicSharedMemorySize,
                         SMEM_TOTAL);

    int dev = 0, smc = 148;
    cudaGetDevice(&dev);
    cudaDeviceGetAttribute(&smc, cudaDevAttrMultiProcessorCount, dev);
    const int ncta = smc * 2;      // all resident: launch_bounds(256,2)

    prep_perm<<<1, 512>>>(lens);
    prep_w<<<(G4 * HD) / 256, 256>>>(W_hh);
    prep_tbl<<<dim3(G4 / 128, NV), 128>>>(emb, W_ih, b_ih, b_hh);
    step0<<<dim3(BT, HD / 128), 128>>>(seq, out);

    lstm_persist<<<ncta, 256, SMEM_TOTAL>>>(seq, out, ncta);
}